// round 2
// baseline (speedup 1.0000x reference)
#include <cuda_runtime.h>
#include <math.h>

#define MAX_E 100000
#define S3 0.5773502691896258f
#define S2 0.7071067811865476f

// Scratch (static device globals: allowed, no runtime allocation)
__device__ float g_h[(size_t)MAX_E * 64];    // 25.6 MB : silu(LN(s@W1+b1))
__device__ float g_w[(size_t)MAX_E * 896];   // 358 MB  : per-edge TP weights

__device__ __forceinline__ float warp_sum(float v) {
#pragma unroll
    for (int o = 16; o > 0; o >>= 1) v += __shfl_xor_sync(0xffffffffu, v, o);
    return v;
}

// ---------------------------------------------------------------------------
// K1: h = silu(LN(edge_scalars @ rad_W1 + b1))  -> g_h
// 64 edges / block, 256 threads. W1 (16KB) staged in smem.
// ---------------------------------------------------------------------------
__global__ __launch_bounds__(256) void k1_rad(
    const float* __restrict__ es, const float* __restrict__ W1,
    const float* __restrict__ b1, const float* __restrict__ lg,
    const float* __restrict__ lb, int E)
{
    __shared__ float s_sm[64 * 65];
    __shared__ float W1_sm[64 * 64];
    __shared__ float red[128];
    const int tid = threadIdx.x;
    const int e0 = blockIdx.x * 64;

    for (int idx = tid; idx < 4096; idx += 256) W1_sm[idx] = W1[idx];
    for (int idx = tid; idx < 4096; idx += 256) {
        int e = idx >> 6, i = idx & 63;
        int ge = e0 + e;
        s_sm[e * 65 + i] = (ge < E) ? es[(size_t)ge * 64 + i] : 0.f;
    }
    __syncthreads();

    const int j = tid & 63, eg = tid >> 6;   // j: output dim, eg: edge group (16 edges each)
    float acc[16];
#pragma unroll
    for (int t = 0; t < 16; t++) acc[t] = 0.f;
    for (int i = 0; i < 64; i++) {
        float w = W1_sm[i * 64 + j];
#pragma unroll
        for (int t = 0; t < 16; t++) acc[t] += s_sm[(eg * 16 + t) * 65 + i] * w;
    }
    const float bj = b1[j];
    __syncthreads();                          // done reading s_sm; reuse as h tile
#pragma unroll
    for (int t = 0; t < 16; t++) s_sm[(eg * 16 + t) * 65 + j] = acc[t] + bj;
    __syncthreads();

    if (tid < 64) {
        float s = 0.f, q = 0.f;
        for (int c = 0; c < 64; c++) { float v = s_sm[tid * 65 + c]; s += v; q += v * v; }
        float mu = s * (1.f / 64.f);
        float var = q * (1.f / 64.f) - mu * mu;
        red[tid] = mu;
        red[64 + tid] = rsqrtf(var + 1e-5f);
    }
    __syncthreads();
    for (int idx = tid; idx < 4096; idx += 256) {
        int e = idx >> 6, c = idx & 63;
        int ge = e0 + e;
        if (ge < E) {
            float v = (s_sm[e * 65 + c] - red[e]) * red[64 + e] * lg[c] + lb[c];
            v = v / (1.f + expf(-v));         // silu
            g_h[(size_t)ge * 64 + c] = v;
        }
    }
}

// ---------------------------------------------------------------------------
// K2: g_w = g_h @ rad_W2 + rad_offset   (E x 64) @ (64 x 896)
// Tile 64(M) x 64(N), K=64 single pass, 4x4 micro-tile per thread.
// ---------------------------------------------------------------------------
__global__ __launch_bounds__(256) void k2_radw(
    const float* __restrict__ W2, const float* __restrict__ off, int E)
{
    __shared__ float h_sm[64 * 65];
    __shared__ float w_sm[64 * 68];
    const int tid = threadIdx.x;
    const int e0 = blockIdx.x * 64;
    const int n0 = blockIdx.y * 64;

    for (int idx = tid; idx < 4096; idx += 256) {
        int e = idx >> 6, k = idx & 63;
        int ge = e0 + e;
        h_sm[e * 65 + k] = (ge < E) ? g_h[(size_t)ge * 64 + k] : 0.f;
    }
    for (int idx = tid; idx < 4096; idx += 256) {
        int k = idx >> 6, c = idx & 63;
        w_sm[k * 68 + c] = W2[(size_t)k * 896 + n0 + c];
    }
    __syncthreads();

    const int tx = tid & 15, ty = tid >> 4;
    float acc[4][4];
#pragma unroll
    for (int i = 0; i < 4; i++)
#pragma unroll
        for (int jq = 0; jq < 4; jq++) acc[i][jq] = 0.f;

    for (int k = 0; k < 64; k++) {
        float a[4], b[4];
#pragma unroll
        for (int i = 0; i < 4; i++) a[i] = h_sm[(ty * 4 + i) * 65 + k];
#pragma unroll
        for (int jq = 0; jq < 4; jq++) b[jq] = w_sm[k * 68 + tx * 4 + jq];
#pragma unroll
        for (int i = 0; i < 4; i++)
#pragma unroll
            for (int jq = 0; jq < 4; jq++) acc[i][jq] += a[i] * b[jq];
    }

    float o[4];
#pragma unroll
    for (int jq = 0; jq < 4; jq++) o[jq] = off[n0 + tx * 4 + jq];
#pragma unroll
    for (int i = 0; i < 4; i++) {
        int ge = e0 + ty * 4 + i;
        if (ge < E) {
            float4 r = make_float4(acc[i][0] + o[0], acc[i][1] + o[1],
                                   acc[i][2] + o[2], acc[i][3] + o[3]);
            *reinterpret_cast<float4*>(&g_w[(size_t)ge * 896 + n0 + tx * 4]) = r;
        }
    }
}

// ---------------------------------------------------------------------------
// K3a: scalar path. s = [x0*y0*wA , (1/sqrt3)*(x1.y1)*wD] @ lin_Ws + bs, then LN.
// 64 edges / block, full N=256, K=384 in 12 chunks of 32. A built on the fly.
// 8x8 micro-tile; layernorm done fully warp-local (warp ty owns edges ty*8..+7).
// ---------------------------------------------------------------------------
__global__ __launch_bounds__(256) void k3a_scalar(
    const float* __restrict__ node, const float* __restrict__ eattr,
    const float* __restrict__ Ws, const float* __restrict__ bs,
    const float* __restrict__ gs, const float* __restrict__ gb,
    float* __restrict__ out, int E)
{
    __shared__ float A_sm[64 * 33];
    __shared__ float W_sm[32 * 256];
    __shared__ float y_sm[64 * 4];
    const int tid = threadIdx.x;
    const int tx = tid & 31, ty = tid >> 5;
    const int e0 = blockIdx.x * 64;

    {
        int e = tid >> 2;
        int ge = e0 + e;
        y_sm[tid] = (ge < E) ? eattr[(size_t)ge * 4 + (tid & 3)] : 0.f;
    }

    float acc[8][8];
#pragma unroll
    for (int i = 0; i < 8; i++)
#pragma unroll
        for (int jq = 0; jq < 8; jq++) acc[i][jq] = 0.f;

    for (int q = 0; q < 12; q++) {
        __syncthreads();
        // build A chunk [64 edges x 32 u]
        for (int idx = tid; idx < 2048; idx += 256) {
            int e = idx >> 5, jj = idx & 31;
            int ge = e0 + e;
            float val = 0.f;
            if (ge < E) {
                if (q < 8) {                      // u in [0,256): x0*y0*wA
                    int u = q * 32 + jj;
                    val = node[(size_t)ge * 640 + u] * y_sm[e * 4] *
                          g_w[(size_t)ge * 896 + u];
                } else {                          // u in [256,384): c3*(x1.y1)*wD
                    int jp = (q - 8) * 32 + jj;
                    const float* xp = node + (size_t)ge * 640 + 256 + 3 * jp;
                    float d = xp[0] * y_sm[e * 4 + 1] + xp[1] * y_sm[e * 4 + 2] +
                              xp[2] * y_sm[e * 4 + 3];
                    val = S3 * d * g_w[(size_t)ge * 896 + 640 + jp];
                }
            }
            A_sm[e * 33 + jj] = val;
        }
        // stage Ws chunk [32 x 256]
        for (int idx = tid; idx < 8192; idx += 256) {
            int k = idx >> 8, c = idx & 255;
            W_sm[idx] = Ws[(size_t)(q * 32 + k) * 256 + c];
        }
        __syncthreads();

        for (int k = 0; k < 32; k++) {
            float a[8], b[8];
#pragma unroll
            for (int i = 0; i < 8; i++) a[i] = A_sm[(ty * 8 + i) * 33 + k];
#pragma unroll
            for (int jq = 0; jq < 8; jq++) b[jq] = W_sm[k * 256 + tx + 32 * jq];
#pragma unroll
            for (int i = 0; i < 8; i++)
#pragma unroll
                for (int jq = 0; jq < 8; jq++) acc[i][jq] += a[i] * b[jq];
        }
    }

    // epilogue: + bias, layernorm over 256 cols (all within warp ty), write
    float bsv[8], gsv[8], gbv[8];
#pragma unroll
    for (int jq = 0; jq < 8; jq++) {
        int c = tx + 32 * jq;
        bsv[jq] = bs[c]; gsv[jq] = gs[c]; gbv[jq] = gb[c];
    }
#pragma unroll
    for (int i = 0; i < 8; i++) {
        float s = 0.f, qq = 0.f;
#pragma unroll
        for (int jq = 0; jq < 8; jq++) {
            float v = acc[i][jq] + bsv[jq];
            acc[i][jq] = v;
            s += v; qq += v * v;
        }
        s = warp_sum(s);
        qq = warp_sum(qq);
        float mu = s * (1.f / 256.f);
        float var = qq * (1.f / 256.f) - mu * mu;
        float rstd = rsqrtf(var + 1e-5f);
        int ge = e0 + ty * 8 + i;
        if (ge < E) {
#pragma unroll
            for (int jq = 0; jq < 8; jq++) {
                int c = tx + 32 * jq;
                out[(size_t)ge * 640 + c] = (acc[i][jq] - mu) * rstd * gsv[jq] + gbv[jq];
            }
        }
    }
}

// ---------------------------------------------------------------------------
// K3b: vector path via algebraic fusion:
//   Ra[e,k]   = sum_{u<256} Wv[u,k]      * x0[e,u]*wB[e,u]
//   Rb[e,k,m] = sum_{u<128} Wv[256+u,k]  * wC[e,u]*x1[e,u,m]
//   Rc[e,k,m] = sum_{u<128} Wv[384+u,k]  * wE[e,u]*x1[e,u,m]
//   v[e,k,:]  = Ra*y1 + y0*Rb + (1/sqrt2)*cross(Rc, y1)
// then norm over all 384 elements (warp-local) and scale by ln_gv[k].
// 16 edges / block, full N=128. 7 accumulator planes, 2x4 micro per thread.
// ---------------------------------------------------------------------------
__global__ __launch_bounds__(256) void k3b_vector(
    const float* __restrict__ node, const float* __restrict__ eattr,
    const float* __restrict__ Wv, const float* __restrict__ gv,
    float* __restrict__ out, int E)
{
    __shared__ float A_sm[3072];       // A1: [e*64+j]; A3: [(e*64+j)*3+m]
    __shared__ float Wv_sm[8192];      // [64 k][128 c]
    __shared__ float y_sm[64];
    const int tid = threadIdx.x;
    const int tx = tid & 31, ty = tid >> 5;
    const int e0 = blockIdx.x * 16;

    if (tid < 64) {
        int e = tid >> 2;
        int ge = e0 + e;
        y_sm[tid] = (ge < E) ? eattr[(size_t)ge * 4 + (tid & 3)] : 0.f;
    }

    float acc[2][4][7];
#pragma unroll
    for (int ii = 0; ii < 2; ii++)
#pragma unroll
        for (int jq = 0; jq < 4; jq++)
#pragma unroll
            for (int p = 0; p < 7; p++) acc[ii][jq][p] = 0.f;

    // ---- Part A: Ra (plane 0), u in [0,256), 4 chunks of 64 ----
    for (int q = 0; q < 4; q++) {
        __syncthreads();
        for (int idx = tid; idx < 1024; idx += 256) {
            int e = idx >> 6, jj = idx & 63;
            int ge = e0 + e;
            int u = q * 64 + jj;
            A_sm[idx] = (ge < E)
                ? node[(size_t)ge * 640 + u] * g_w[(size_t)ge * 896 + 256 + u]
                : 0.f;
        }
        for (int idx = tid; idx < 8192; idx += 256)
            Wv_sm[idx] = Wv[(size_t)(q * 64) * 128 + idx];
        __syncthreads();
        for (int k = 0; k < 64; k++) {
            float b[4];
#pragma unroll
            for (int jq = 0; jq < 4; jq++) b[jq] = Wv_sm[k * 128 + tx + 32 * jq];
            float a0 = A_sm[ty * 64 + k];
            float a1 = A_sm[(ty + 8) * 64 + k];
#pragma unroll
            for (int jq = 0; jq < 4; jq++) {
                acc[0][jq][0] += a0 * b[jq];
                acc[1][jq][0] += a1 * b[jq];
            }
        }
    }

    // ---- Parts B (planes 1..3, wC, Wv rows 256+) and C (planes 4..6, wE, rows 384+) ----
#pragma unroll
    for (int part = 0; part < 2; part++) {
        const int wofs = (part == 0) ? 512 : 768;
        const int vrow = (part == 0) ? 256 : 384;
        const int pb = (part == 0) ? 1 : 4;
        for (int q = 0; q < 2; q++) {
            __syncthreads();
            for (int idx = tid; idx < 1024; idx += 256) {
                int e = idx >> 6, jj = idx & 63;
                int ge = e0 + e;
                int jp = q * 64 + jj;
                float w = 0.f, x0v = 0.f, x1v = 0.f, x2v = 0.f;
                if (ge < E) {
                    w = g_w[(size_t)ge * 896 + wofs + jp];
                    const float* xp = node + (size_t)ge * 640 + 256 + 3 * jp;
                    x0v = xp[0]; x1v = xp[1]; x2v = xp[2];
                }
                A_sm[idx * 3 + 0] = x0v * w;
                A_sm[idx * 3 + 1] = x1v * w;
                A_sm[idx * 3 + 2] = x2v * w;
            }
            for (int idx = tid; idx < 8192; idx += 256)
                Wv_sm[idx] = Wv[(size_t)(vrow + q * 64) * 128 + idx];
            __syncthreads();
            for (int k = 0; k < 64; k++) {
                float b[4];
#pragma unroll
                for (int jq = 0; jq < 4; jq++) b[jq] = Wv_sm[k * 128 + tx + 32 * jq];
                int ba = (ty * 64 + k) * 3, bb = ((ty + 8) * 64 + k) * 3;
                float a00 = A_sm[ba], a01 = A_sm[ba + 1], a02 = A_sm[ba + 2];
                float a10 = A_sm[bb], a11 = A_sm[bb + 1], a12 = A_sm[bb + 2];
#pragma unroll
                for (int jq = 0; jq < 4; jq++) {
                    acc[0][jq][pb + 0] += a00 * b[jq];
                    acc[0][jq][pb + 1] += a01 * b[jq];
                    acc[0][jq][pb + 2] += a02 * b[jq];
                    acc[1][jq][pb + 0] += a10 * b[jq];
                    acc[1][jq][pb + 1] += a11 * b[jq];
                    acc[1][jq][pb + 2] += a12 * b[jq];
                }
            }
        }
    }

    // ---- Combine + norm + write ----
    float gvv[4];
#pragma unroll
    for (int jq = 0; jq < 4; jq++) gvv[jq] = gv[tx + 32 * jq];

#pragma unroll
    for (int ii = 0; ii < 2; ii++) {
        int e = ty + 8 * ii;
        int ge = e0 + e;
        float ya = y_sm[e * 4 + 0];
        float y0v = y_sm[e * 4 + 1], y1v = y_sm[e * 4 + 2], y2v = y_sm[e * 4 + 3];
        float v[4][3];
        float sq = 0.f;
#pragma unroll
        for (int jq = 0; jq < 4; jq++) {
            float Ra = acc[ii][jq][0];
            float rb0 = acc[ii][jq][1], rb1 = acc[ii][jq][2], rb2 = acc[ii][jq][3];
            float rc0 = acc[ii][jq][4], rc1 = acc[ii][jq][5], rc2 = acc[ii][jq][6];
            float cr0 = rc1 * y2v - rc2 * y1v;
            float cr1 = rc2 * y0v - rc0 * y2v;
            float cr2 = rc0 * y1v - rc1 * y0v;
            v[jq][0] = Ra * y0v + ya * rb0 + S2 * cr0;
            v[jq][1] = Ra * y1v + ya * rb1 + S2 * cr1;
            v[jq][2] = Ra * y2v + ya * rb2 + S2 * cr2;
            sq += v[jq][0] * v[jq][0] + v[jq][1] * v[jq][1] + v[jq][2] * v[jq][2];
        }
        sq = warp_sum(sq);                    // warp ty owns all 128 cols of edge e
        float rstd = rsqrtf(sq * (1.f / 384.f) + 1e-5f);
        if (ge < E) {
#pragma unroll
            for (int jq = 0; jq < 4; jq++) {
                size_t base = (size_t)ge * 640 + 256 + 3 * (size_t)(tx + 32 * jq);
                out[base + 0] = v[jq][0] * rstd * gvv[jq];
                out[base + 1] = v[jq][1] * rstd * gvv[jq];
                out[base + 2] = v[jq][2] * rstd * gvv[jq];
            }
        }
    }
}

// ---------------------------------------------------------------------------
extern "C" void kernel_launch(void* const* d_in, const int* in_sizes, int n_in,
                              void* d_out, int out_size)
{
    const float* node  = (const float*)d_in[0];   // (E, 640)
    const float* eattr = (const float*)d_in[1];   // (E, 4)
    const float* escal = (const float*)d_in[2];   // (E, 64)
    const float* rW1   = (const float*)d_in[3];   // (64, 64)
    const float* rb1   = (const float*)d_in[4];   // (64,)
    const float* rlg   = (const float*)d_in[5];   // (64,)
    const float* rlb   = (const float*)d_in[6];   // (64,)
    const float* rW2   = (const float*)d_in[7];   // (64, 896)
    const float* roff  = (const float*)d_in[8];   // (896,)
    const float* Ws    = (const float*)d_in[9];   // (384, 256)
    const float* bs    = (const float*)d_in[10];  // (256,)
    const float* Wv    = (const float*)d_in[11];  // (512, 128)
    const float* gs    = (const float*)d_in[12];  // (256,)
    const float* gb    = (const float*)d_in[13];  // (256,)
    const float* gv    = (const float*)d_in[14];  // (128,)
    float* out = (float*)d_out;

    const int E = in_sizes[1] / 4;
    const int nb64 = (E + 63) / 64;
    const int nb16 = (E + 15) / 16;

    k1_rad<<<nb64, 256>>>(escal, rW1, rb1, rlg, rlb, E);
    dim3 g2(nb64, 14);
    k2_radw<<<g2, 256>>>(rW2, roff, E);
    k3a_scalar<<<nb64, 256>>>(node, eattr, Ws, bs, gs, gb, out, E);
    k3b_vector<<<nb16, 256>>>(node, eattr, Wv, gv, out, E);
}

// round 3
// speedup vs baseline: 1.4784x; 1.4784x over previous
#include <cuda_runtime.h>
#include <math.h>

#define MAX_E 100000
#define S3 0.5773502691896258f
#define S2 0.7071067811865476f

// Scratch (static device globals: allowed, no runtime allocation)
__device__ float g_h[(size_t)MAX_E * 64];    // 25.6 MB : silu(LN(s@W1+b1))
__device__ float g_w[(size_t)MAX_E * 896];   // 358 MB  : per-edge TP weights

__device__ __forceinline__ float warp_sum(float v) {
#pragma unroll
    for (int o = 16; o > 0; o >>= 1) v += __shfl_xor_sync(0xffffffffu, v, o);
    return v;
}

// ---------------------------------------------------------------------------
// K1: h = silu(LN(edge_scalars @ rad_W1 + b1))  -> g_h
// 64 edges / block, 256 threads. W1 (16KB) staged in smem.
// ---------------------------------------------------------------------------
__global__ __launch_bounds__(256) void k1_rad(
    const float* __restrict__ es, const float* __restrict__ W1,
    const float* __restrict__ b1, const float* __restrict__ lg,
    const float* __restrict__ lb, int E)
{
    __shared__ float s_sm[64 * 65];
    __shared__ float W1_sm[64 * 64];
    __shared__ float red[128];
    const int tid = threadIdx.x;
    const int e0 = blockIdx.x * 64;

    for (int idx = tid; idx < 4096; idx += 256) W1_sm[idx] = W1[idx];
    for (int idx = tid; idx < 4096; idx += 256) {
        int e = idx >> 6, i = idx & 63;
        int ge = e0 + e;
        s_sm[e * 65 + i] = (ge < E) ? es[(size_t)ge * 64 + i] : 0.f;
    }
    __syncthreads();

    const int j = tid & 63, eg = tid >> 6;   // j: output dim, eg: edge group (16 edges each)
    float acc[16];
#pragma unroll
    for (int t = 0; t < 16; t++) acc[t] = 0.f;
    for (int i = 0; i < 64; i++) {
        float w = W1_sm[i * 64 + j];
#pragma unroll
        for (int t = 0; t < 16; t++) acc[t] += s_sm[(eg * 16 + t) * 65 + i] * w;
    }
    const float bj = b1[j];
    __syncthreads();                          // done reading s_sm; reuse as h tile
#pragma unroll
    for (int t = 0; t < 16; t++) s_sm[(eg * 16 + t) * 65 + j] = acc[t] + bj;
    __syncthreads();

    if (tid < 64) {
        float s = 0.f, q = 0.f;
        for (int c = 0; c < 64; c++) { float v = s_sm[tid * 65 + c]; s += v; q += v * v; }
        float mu = s * (1.f / 64.f);
        float var = q * (1.f / 64.f) - mu * mu;
        red[tid] = mu;
        red[64 + tid] = rsqrtf(var + 1e-5f);
    }
    __syncthreads();
    for (int idx = tid; idx < 4096; idx += 256) {
        int e = idx >> 6, c = idx & 63;
        int ge = e0 + e;
        if (ge < E) {
            float v = (s_sm[e * 65 + c] - red[e]) * red[64 + e] * lg[c] + lb[c];
            v = v / (1.f + expf(-v));         // silu
            g_h[(size_t)ge * 64 + c] = v;
        }
    }
}

// ---------------------------------------------------------------------------
// K2: g_w = g_h @ rad_W2 + rad_offset   (E x 64) @ (64 x 896)
// Tile 64(M) x 64(N), K=64 single pass, 4x4 micro-tile per thread.
// ---------------------------------------------------------------------------
__global__ __launch_bounds__(256) void k2_radw(
    const float* __restrict__ W2, const float* __restrict__ off, int E)
{
    __shared__ float h_sm[64 * 65];
    __shared__ float w_sm[64 * 68];
    const int tid = threadIdx.x;
    const int e0 = blockIdx.x * 64;
    const int n0 = blockIdx.y * 64;

    for (int idx = tid; idx < 4096; idx += 256) {
        int e = idx >> 6, k = idx & 63;
        int ge = e0 + e;
        h_sm[e * 65 + k] = (ge < E) ? g_h[(size_t)ge * 64 + k] : 0.f;
    }
    for (int idx = tid; idx < 4096; idx += 256) {
        int k = idx >> 6, c = idx & 63;
        w_sm[k * 68 + c] = W2[(size_t)k * 896 + n0 + c];
    }
    __syncthreads();

    const int tx = tid & 15, ty = tid >> 4;
    float acc[4][4];
#pragma unroll
    for (int i = 0; i < 4; i++)
#pragma unroll
        for (int jq = 0; jq < 4; jq++) acc[i][jq] = 0.f;

    for (int k = 0; k < 64; k++) {
        float a[4], b[4];
#pragma unroll
        for (int i = 0; i < 4; i++) a[i] = h_sm[(ty * 4 + i) * 65 + k];
#pragma unroll
        for (int jq = 0; jq < 4; jq++) b[jq] = w_sm[k * 68 + tx * 4 + jq];
#pragma unroll
        for (int i = 0; i < 4; i++)
#pragma unroll
            for (int jq = 0; jq < 4; jq++) acc[i][jq] += a[i] * b[jq];
    }

    float o[4];
#pragma unroll
    for (int jq = 0; jq < 4; jq++) o[jq] = off[n0 + tx * 4 + jq];
#pragma unroll
    for (int i = 0; i < 4; i++) {
        int ge = e0 + ty * 4 + i;
        if (ge < E) {
            float4 r = make_float4(acc[i][0] + o[0], acc[i][1] + o[1],
                                   acc[i][2] + o[2], acc[i][3] + o[3]);
            *reinterpret_cast<float4*>(&g_w[(size_t)ge * 896 + n0 + tx * 4]) = r;
        }
    }
}

// ---------------------------------------------------------------------------
// K3a: scalar path. s = [x0*y0*wA , (1/sqrt3)*(x1.y1)*wD] @ lin_Ws + bs, then LN.
// 64 edges / block, full N=256, K=384 in 12 chunks of 32. A built on the fly.
// 8x8 micro-tile; layernorm done fully warp-local (warp ty owns edges ty*8..+7).
// ---------------------------------------------------------------------------
__global__ __launch_bounds__(256) void k3a_scalar(
    const float* __restrict__ node, const float* __restrict__ eattr,
    const float* __restrict__ Ws, const float* __restrict__ bs,
    const float* __restrict__ gs, const float* __restrict__ gb,
    float* __restrict__ out, int E)
{
    __shared__ float A_sm[64 * 33];
    __shared__ float W_sm[32 * 256];
    __shared__ float y_sm[64 * 4];
    const int tid = threadIdx.x;
    const int tx = tid & 31, ty = tid >> 5;
    const int e0 = blockIdx.x * 64;

    {
        int e = tid >> 2;
        int ge = e0 + e;
        y_sm[tid] = (ge < E) ? eattr[(size_t)ge * 4 + (tid & 3)] : 0.f;
    }

    float acc[8][8];
#pragma unroll
    for (int i = 0; i < 8; i++)
#pragma unroll
        for (int jq = 0; jq < 8; jq++) acc[i][jq] = 0.f;

    for (int q = 0; q < 12; q++) {
        __syncthreads();
        // build A chunk [64 edges x 32 u]
        for (int idx = tid; idx < 2048; idx += 256) {
            int e = idx >> 5, jj = idx & 31;
            int ge = e0 + e;
            float val = 0.f;
            if (ge < E) {
                if (q < 8) {                      // u in [0,256): x0*y0*wA
                    int u = q * 32 + jj;
                    val = node[(size_t)ge * 640 + u] * y_sm[e * 4] *
                          g_w[(size_t)ge * 896 + u];
                } else {                          // u in [256,384): c3*(x1.y1)*wD
                    int jp = (q - 8) * 32 + jj;
                    const float* xp = node + (size_t)ge * 640 + 256 + 3 * jp;
                    float d = xp[0] * y_sm[e * 4 + 1] + xp[1] * y_sm[e * 4 + 2] +
                              xp[2] * y_sm[e * 4 + 3];
                    val = S3 * d * g_w[(size_t)ge * 896 + 640 + jp];
                }
            }
            A_sm[e * 33 + jj] = val;
        }
        // stage Ws chunk [32 x 256]
        for (int idx = tid; idx < 8192; idx += 256) {
            int k = idx >> 8, c = idx & 255;
            W_sm[idx] = Ws[(size_t)(q * 32 + k) * 256 + c];
        }
        __syncthreads();

        for (int k = 0; k < 32; k++) {
            float a[8], b[8];
#pragma unroll
            for (int i = 0; i < 8; i++) a[i] = A_sm[(ty * 8 + i) * 33 + k];
#pragma unroll
            for (int jq = 0; jq < 8; jq++) b[jq] = W_sm[k * 256 + tx + 32 * jq];
#pragma unroll
            for (int i = 0; i < 8; i++)
#pragma unroll
                for (int jq = 0; jq < 8; jq++) acc[i][jq] += a[i] * b[jq];
        }
    }

    // epilogue: + bias, layernorm over 256 cols (all within warp ty), write
    float bsv[8], gsv[8], gbv[8];
#pragma unroll
    for (int jq = 0; jq < 8; jq++) {
        int c = tx + 32 * jq;
        bsv[jq] = bs[c]; gsv[jq] = gs[c]; gbv[jq] = gb[c];
    }
#pragma unroll
    for (int i = 0; i < 8; i++) {
        float s = 0.f, qq = 0.f;
#pragma unroll
        for (int jq = 0; jq < 8; jq++) {
            float v = acc[i][jq] + bsv[jq];
            acc[i][jq] = v;
            s += v; qq += v * v;
        }
        s = warp_sum(s);
        qq = warp_sum(qq);
        float mu = s * (1.f / 256.f);
        float var = qq * (1.f / 256.f) - mu * mu;
        float rstd = rsqrtf(var + 1e-5f);
        int ge = e0 + ty * 8 + i;
        if (ge < E) {
#pragma unroll
            for (int jq = 0; jq < 8; jq++) {
                int c = tx + 32 * jq;
                out[(size_t)ge * 640 + c] = (acc[i][jq] - mu) * rstd * gsv[jq] + gbv[jq];
            }
        }
    }
}

// ---------------------------------------------------------------------------
// K3b: vector path via algebraic fusion:
//   Ra[e,k]   = sum_{u<256} Wv[u,k]      * x0[e,u]*wB[e,u]
//   Rb[e,k,m] = sum_{u<128} Wv[256+u,k]  * wC[e,u]*x1[e,u,m]
//   Rc[e,k,m] = sum_{u<128} Wv[384+u,k]  * wE[e,u]*x1[e,u,m]
//   v[e,k,:]  = Ra*y1 + y0*Rb + (1/sqrt2)*cross(Rc, y1)
// then norm over all 384 elements (warp-local) and scale by ln_gv[k].
// 16 edges / block, full N=128. 7 accumulator planes, 2x4 micro per thread.
// ---------------------------------------------------------------------------
__global__ __launch_bounds__(256) void k3b_vector(
    const float* __restrict__ node, const float* __restrict__ eattr,
    const float* __restrict__ Wv, const float* __restrict__ gv,
    float* __restrict__ out, int E)
{
    __shared__ float A_sm[3072];       // A1: [e*64+j]; A3: [(e*64+j)*3+m]
    __shared__ float Wv_sm[8192];      // [64 k][128 c]
    __shared__ float y_sm[64];
    const int tid = threadIdx.x;
    const int tx = tid & 31, ty = tid >> 5;
    const int e0 = blockIdx.x * 16;

    if (tid < 64) {
        int e = tid >> 2;
        int ge = e0 + e;
        y_sm[tid] = (ge < E) ? eattr[(size_t)ge * 4 + (tid & 3)] : 0.f;
    }

    float acc[2][4][7];
#pragma unroll
    for (int ii = 0; ii < 2; ii++)
#pragma unroll
        for (int jq = 0; jq < 4; jq++)
#pragma unroll
            for (int p = 0; p < 7; p++) acc[ii][jq][p] = 0.f;

    // ---- Part A: Ra (plane 0), u in [0,256), 4 chunks of 64 ----
    for (int q = 0; q < 4; q++) {
        __syncthreads();
        for (int idx = tid; idx < 1024; idx += 256) {
            int e = idx >> 6, jj = idx & 63;
            int ge = e0 + e;
            int u = q * 64 + jj;
            A_sm[idx] = (ge < E)
                ? node[(size_t)ge * 640 + u] * g_w[(size_t)ge * 896 + 256 + u]
                : 0.f;
        }
        for (int idx = tid; idx < 8192; idx += 256)
            Wv_sm[idx] = Wv[(size_t)(q * 64) * 128 + idx];
        __syncthreads();
        for (int k = 0; k < 64; k++) {
            float b[4];
#pragma unroll
            for (int jq = 0; jq < 4; jq++) b[jq] = Wv_sm[k * 128 + tx + 32 * jq];
            float a0 = A_sm[ty * 64 + k];
            float a1 = A_sm[(ty + 8) * 64 + k];
#pragma unroll
            for (int jq = 0; jq < 4; jq++) {
                acc[0][jq][0] += a0 * b[jq];
                acc[1][jq][0] += a1 * b[jq];
            }
        }
    }

    // ---- Parts B (planes 1..3, wC, Wv rows 256+) and C (planes 4..6, wE, rows 384+) ----
#pragma unroll
    for (int part = 0; part < 2; part++) {
        const int wofs = (part == 0) ? 512 : 768;
        const int vrow = (part == 0) ? 256 : 384;
        const int pb = (part == 0) ? 1 : 4;
        for (int q = 0; q < 2; q++) {
            __syncthreads();
            for (int idx = tid; idx < 1024; idx += 256) {
                int e = idx >> 6, jj = idx & 63;
                int ge = e0 + e;
                int jp = q * 64 + jj;
                float w = 0.f, x0v = 0.f, x1v = 0.f, x2v = 0.f;
                if (ge < E) {
                    w = g_w[(size_t)ge * 896 + wofs + jp];
                    const float* xp = node + (size_t)ge * 640 + 256 + 3 * jp;
                    x0v = xp[0]; x1v = xp[1]; x2v = xp[2];
                }
                A_sm[idx * 3 + 0] = x0v * w;
                A_sm[idx * 3 + 1] = x1v * w;
                A_sm[idx * 3 + 2] = x2v * w;
            }
            for (int idx = tid; idx < 8192; idx += 256)
                Wv_sm[idx] = Wv[(size_t)(vrow + q * 64) * 128 + idx];
            __syncthreads();
            for (int k = 0; k < 64; k++) {
                float b[4];
#pragma unroll
                for (int jq = 0; jq < 4; jq++) b[jq] = Wv_sm[k * 128 + tx + 32 * jq];
                int ba = (ty * 64 + k) * 3, bb = ((ty + 8) * 64 + k) * 3;
                float a00 = A_sm[ba], a01 = A_sm[ba + 1], a02 = A_sm[ba + 2];
                float a10 = A_sm[bb], a11 = A_sm[bb + 1], a12 = A_sm[bb + 2];
#pragma unroll
                for (int jq = 0; jq < 4; jq++) {
                    acc[0][jq][pb + 0] += a00 * b[jq];
                    acc[0][jq][pb + 1] += a01 * b[jq];
                    acc[0][jq][pb + 2] += a02 * b[jq];
                    acc[1][jq][pb + 0] += a10 * b[jq];
                    acc[1][jq][pb + 1] += a11 * b[jq];
                    acc[1][jq][pb + 2] += a12 * b[jq];
                }
            }
        }
    }

    // ---- Combine + norm + write ----
    float gvv[4];
#pragma unroll
    for (int jq = 0; jq < 4; jq++) gvv[jq] = gv[tx + 32 * jq];

#pragma unroll
    for (int ii = 0; ii < 2; ii++) {
        int e = ty + 8 * ii;
        int ge = e0 + e;
        float ya = y_sm[e * 4 + 0];
        float y0v = y_sm[e * 4 + 1], y1v = y_sm[e * 4 + 2], y2v = y_sm[e * 4 + 3];
        float v[4][3];
        float sq = 0.f;
#pragma unroll
        for (int jq = 0; jq < 4; jq++) {
            float Ra = acc[ii][jq][0];
            float rb0 = acc[ii][jq][1], rb1 = acc[ii][jq][2], rb2 = acc[ii][jq][3];
            float rc0 = acc[ii][jq][4], rc1 = acc[ii][jq][5], rc2 = acc[ii][jq][6];
            float cr0 = rc1 * y2v - rc2 * y1v;
            float cr1 = rc2 * y0v - rc0 * y2v;
            float cr2 = rc0 * y1v - rc1 * y0v;
            v[jq][0] = Ra * y0v + ya * rb0 + S2 * cr0;
            v[jq][1] = Ra * y1v + ya * rb1 + S2 * cr1;
            v[jq][2] = Ra * y2v + ya * rb2 + S2 * cr2;
            sq += v[jq][0] * v[jq][0] + v[jq][1] * v[jq][1] + v[jq][2] * v[jq][2];
        }
        sq = warp_sum(sq);                    // warp ty owns all 128 cols of edge e
        float rstd = rsqrtf(sq * (1.f / 384.f) + 1e-5f);
        if (ge < E) {
#pragma unroll
            for (int jq = 0; jq < 4; jq++) {
                size_t base = (size_t)ge * 640 + 256 + 3 * (size_t)(tx + 32 * jq);
                out[base + 0] = v[jq][0] * rstd * gvv[jq];
                out[base + 1] = v[jq][1] * rstd * gvv[jq];
                out[base + 2] = v[jq][2] * rstd * gvv[jq];
            }
        }
    }
}

// ---------------------------------------------------------------------------
extern "C" void kernel_launch(void* const* d_in, const int* in_sizes, int n_in,
                              void* d_out, int out_size)
{
    const float* node  = (const float*)d_in[0];   // (E, 640)
    const float* eattr = (const float*)d_in[1];   // (E, 4)
    const float* escal = (const float*)d_in[2];   // (E, 64)
    const float* rW1   = (const float*)d_in[3];   // (64, 64)
    const float* rb1   = (const float*)d_in[4];   // (64,)
    const float* rlg   = (const float*)d_in[5];   // (64,)
    const float* rlb   = (const float*)d_in[6];   // (64,)
    const float* rW2   = (const float*)d_in[7];   // (64, 896)
    const float* roff  = (const float*)d_in[8];   // (896,)
    const float* Ws    = (const float*)d_in[9];   // (384, 256)
    const float* bs    = (const float*)d_in[10];  // (256,)
    const float* Wv    = (const float*)d_in[11];  // (512, 128)
    const float* gs    = (const float*)d_in[12];  // (256,)
    const float* gb    = (const float*)d_in[13];  // (256,)
    const float* gv    = (const float*)d_in[14];  // (128,)
    float* out = (float*)d_out;

    const int E = in_sizes[1] / 4;
    const int nb64 = (E + 63) / 64;
    const int nb16 = (E + 15) / 16;

    k1_rad<<<nb64, 256>>>(escal, rW1, rb1, rlg, rlb, E);
    dim3 g2(nb64, 14);
    k2_radw<<<g2, 256>>>(rW2, roff, E);
    k3a_scalar<<<nb64, 256>>>(node, eattr, Ws, bs, gs, gb, out, E);
    k3b_vector<<<nb16, 256>>>(node, eattr, Wv, gv, out, E);
}